// round 16
// baseline (speedup 1.0000x reference)
#include <cuda_runtime.h>
#include <cuda_fp16.h>
#include <cstdint>

#define BB 4
#define LL 2048
#define DD 1024
#define HH 16
#define DKH 64
#define GK 1024
#define GN 1024

// ---------------- bitcast helpers ----------------
__device__ __forceinline__ uint32_t h2u(__half2 h) {
    uint32_t u;
    *reinterpret_cast<__half2*>(&u) = h;
    return u;
}
__device__ __forceinline__ __half2 u2h(uint32_t u) {
    return *reinterpret_cast<__half2*>(&u);
}

// ---------------- scratch (static device allocations) ----------------
__device__ __half g_qx  [(size_t)BB * LL * DD];
__device__ __half g_kx  [(size_t)BB * LL * DD];
__device__ __half g_vx  [(size_t)BB * LL * DD];
__device__ __half g_sx  [(size_t)BB * LL * DD];
__device__ __half g_wq  [(size_t)DD * DD];
__device__ __half g_wk  [(size_t)DD * DD];
__device__ __half g_wv  [(size_t)DD * DD];
__device__ __half g_ws  [(size_t)DD * DD];
__device__ __half g_wo  [(size_t)DD * DD];
__device__ __half g_semo[(size_t)BB * LL * DD];
__device__ __half g_qp  [(size_t)BB * LL * DD];
__device__ __half g_kp  [(size_t)BB * LL * DD];
__device__ __half g_vp  [(size_t)BB * LL * DD];
__device__ __half g_op  [(size_t)BB * LL * DD];

// ---------------- PTX helpers ----------------
__device__ __forceinline__ void cpa16h(uint32_t saddr, const __half* src) {
    asm volatile("cp.async.cg.shared.global [%0], [%1], 16;\n" :: "r"(saddr), "l"(src));
}
__device__ __forceinline__ uint32_t smem_u32(const void* p) {
    uint32_t a;
    asm("{ .reg .u64 t; cvta.to.shared.u64 t, %1; cvt.u32.u64 %0, t; }" : "=r"(a) : "l"(p));
    return a;
}
__device__ __forceinline__ void mma16816(float* d, const uint32_t* a, uint32_t b0, uint32_t b1) {
    asm volatile(
        "mma.sync.aligned.m16n8k16.row.col.f32.f16.f16.f32 "
        "{%0,%1,%2,%3}, {%4,%5,%6,%7}, {%8,%9}, {%0,%1,%2,%3};"
        : "+f"(d[0]), "+f"(d[1]), "+f"(d[2]), "+f"(d[3])
        : "r"(a[0]), "r"(a[1]), "r"(a[2]), "r"(a[3]), "r"(b0), "r"(b1));
}
__device__ __forceinline__ void ldmx4(uint32_t& r0, uint32_t& r1, uint32_t& r2, uint32_t& r3,
                                      uint32_t addr) {
    asm volatile("ldmatrix.sync.aligned.m8n8.x4.shared.b16 {%0,%1,%2,%3}, [%4];"
                 : "=r"(r0), "=r"(r1), "=r"(r2), "=r"(r3) : "r"(addr));
}
__device__ __forceinline__ void ldmx4t(uint32_t& r0, uint32_t& r1, uint32_t& r2, uint32_t& r3,
                                       uint32_t addr) {
    asm volatile("ldmatrix.sync.aligned.m8n8.x4.trans.shared.b16 {%0,%1,%2,%3}, [%4];"
                 : "=r"(r0), "=r"(r1), "=r"(r2), "=r"(r3) : "r"(addr));
}
__device__ __forceinline__ void stg_cs_f2(void* p, float x, float y) {
    asm volatile("st.global.cs.v2.f32 [%0], {%1,%2};" :: "l"(p), "f"(x), "f"(y) : "memory");
}

// ================= fused f32 -> f16 conversion (single launch) =================
struct CvtArgs {
    const float4* src[9];
    uint4*        dst[9];
};
__global__ __launch_bounds__(256) void cvt_all(CvtArgs a)
{
    int bid = blockIdx.x;
    const float4* s;
    uint4* d;
    size_t i;
    if (bid < 16384) {
        int t = bid >> 12;
        s = a.src[t]; d = a.dst[t];
        i = (size_t)(bid & 4095) * 256 + threadIdx.x;
    } else {
        int t = 4 + ((bid - 16384) >> 9);
        s = a.src[t]; d = a.dst[t];
        i = (size_t)((bid - 16384) & 511) * 256 + threadIdx.x;
    }
    float4 x = s[i * 2], y = s[i * 2 + 1];
    uint4 o;
    o.x = h2u(__floats2half2_rn(x.x, x.y));
    o.y = h2u(__floats2half2_rn(x.z, x.w));
    o.z = h2u(__floats2half2_rn(y.x, y.y));
    o.w = h2u(__floats2half2_rn(y.z, y.w));
    d[i] = o;
}

// ===== fp16 GEMM, 128x128 tile, BK=32, 4 stages — raw ldmatrix + mma (R14) =====
#define HBM 128
#define HBN 128
#define HBK 32
#define HPAD 40
#define HNST 4
#define HNT (GK / HBK)
#define HSTG ((HBM + HBN) * HPAD)
#define HCPAD 132
#define HSMEM_BYTES (HNST * HSTG * 2)   // 81920

template <typename OutT>
__device__ __forceinline__ void gemm_core(
    const __half* __restrict__ X, const __half* __restrict__ W,
    const float* __restrict__ bias, const __half* __restrict__ addend,
    OutT* __restrict__ C, __half* hsm, int m0, int n0)
{
    const int tid  = threadIdx.x;
    const int wid  = tid >> 5;
    const int lane = tid & 31;
    const int warp_m = wid & 3;
    const int warp_n = wid >> 2;
    const int si   = lane & 7;
    const int gid  = lane >> 2;
    const int tig  = lane & 3;
    const uint32_t smb = smem_u32(hsm);

    float cacc[2][4][8];
    #pragma unroll
    for (int mt = 0; mt < 2; mt++)
        #pragma unroll
        for (int nt = 0; nt < 4; nt++)
            #pragma unroll
            for (int j = 0; j < 8; j++) cacc[mt][nt][j] = 0.0f;

    auto stage = [&](int s, int k0) {
        uint32_t base = smb + (uint32_t)(s * HSTG) * 2;
        #pragma unroll
        for (int j = 0; j < 4; j++) {
            int idx = tid + 256 * j;
            if (idx < 512) {
                int r = idx >> 2, c8 = (idx & 3) * 8;
                cpa16h(base + (uint32_t)(r * HPAD + c8) * 2,
                       X + (size_t)(m0 + r) * GK + k0 + c8);
            } else {
                int i2 = idx - 512;
                int r = i2 >> 2, c8 = (i2 & 3) * 8;
                cpa16h(base + (uint32_t)((HBM + r) * HPAD + c8) * 2,
                       W + (size_t)(n0 + r) * GK + k0 + c8);
            }
        }
        asm volatile("cp.async.commit_group;\n");
    };

    #pragma unroll
    for (int s = 0; s < HNST - 1; s++) stage(s, s * HBK);

    const int a_roff = ((lane >> 3) & 1) * 8;
    const int a_coff = ((lane >> 4) & 1) * 8;
    const int b_roff = ((lane >> 4) & 1) * 8;
    const int b_coff = ((lane >> 3) & 1) * 8;

    for (int kt = 0; kt < HNT; kt++) {
        asm volatile("cp.async.wait_group %0;\n" :: "n"(HNST - 2));
        __syncthreads();

        const int ld = kt + HNST - 1;
        if (ld < HNT) stage(ld % HNST, ld * HBK);
        else asm volatile("cp.async.commit_group;\n");

        const uint32_t sbase = smb + (uint32_t)((kt % HNST) * HSTG) * 2;

        #pragma unroll
        for (int kk = 0; kk < HBK; kk += 16) {
            uint32_t a[2][4], bf[4][4];
            #pragma unroll
            for (int mt = 0; mt < 2; mt++) {
                int row = warp_m * 32 + mt * 16 + a_roff + si;
                int col = kk + a_coff;
                ldmx4(a[mt][0], a[mt][1], a[mt][2], a[mt][3],
                      sbase + (uint32_t)(row * HPAD + col) * 2);
            }
            #pragma unroll
            for (int nt = 0; nt < 4; nt++) {
                int row = HBM + warp_n * 64 + nt * 16 + b_roff + si;
                int col = kk + b_coff;
                ldmx4(bf[nt][0], bf[nt][1], bf[nt][2], bf[nt][3],
                      sbase + (uint32_t)(row * HPAD + col) * 2);
            }
            #pragma unroll
            for (int mt = 0; mt < 2; mt++)
                #pragma unroll
                for (int nt = 0; nt < 4; nt++) {
                    mma16816(&cacc[mt][nt][0], a[mt], bf[nt][0], bf[nt][1]);
                    mma16816(&cacc[mt][nt][4], a[mt], bf[nt][2], bf[nt][3]);
                }
        }
    }

    asm volatile("cp.async.wait_group 0;\n");
    __syncthreads();

    float* Cs = (float*)hsm;
    #pragma unroll
    for (int mt = 0; mt < 2; mt++)
        #pragma unroll
        for (int nt = 0; nt < 4; nt++) {
            int rw = warp_m * 32 + mt * 16 + gid;
            int cb = warp_n * 64 + nt * 16 + tig * 2;
            Cs[rw * HCPAD + cb]           = cacc[mt][nt][0];
            Cs[rw * HCPAD + cb + 1]       = cacc[mt][nt][1];
            Cs[(rw + 8) * HCPAD + cb]     = cacc[mt][nt][2];
            Cs[(rw + 8) * HCPAD + cb + 1] = cacc[mt][nt][3];
            Cs[rw * HCPAD + cb + 8]       = cacc[mt][nt][4];
            Cs[rw * HCPAD + cb + 9]       = cacc[mt][nt][5];
            Cs[(rw + 8) * HCPAD + cb + 8] = cacc[mt][nt][6];
            Cs[(rw + 8) * HCPAD + cb + 9] = cacc[mt][nt][7];
        }
    __syncthreads();

    const int c4 = (tid & 31) * 4;
    const int r0 = tid >> 5;
    float4 bv = *(const float4*)(bias + n0 + c4);
    #pragma unroll
    for (int it = 0; it < 16; it++) {
        int rr = r0 + it * 8;
        size_t gi = (size_t)(m0 + rr) * GN + n0 + c4;
        float4 val = *(const float4*)(Cs + rr * HCPAD + c4);
        val.x += bv.x; val.y += bv.y; val.z += bv.z; val.w += bv.w;
        if (addend) {
            uint2 au = *(const uint2*)(addend + gi);
            __half2 a01 = u2h(au.x), a23 = u2h(au.y);
            val.x += __low2float(a01);  val.y += __high2float(a01);
            val.z += __low2float(a23);  val.w += __high2float(a23);
        }
        if (sizeof(OutT) == 2) {
            uint2 o;
            o.x = h2u(__floats2half2_rn(val.x, val.y));
            o.y = h2u(__floats2half2_rn(val.z, val.w));
            *(uint2*)((__half*)C + gi) = o;
        } else {
            *(float4*)((float*)C + gi) = val;
        }
    }
}

template <typename OutT>
__global__ __launch_bounds__(256, 2) void gemm_h(
    const __half* __restrict__ X, const __half* __restrict__ W,
    const float* __restrict__ bias, const __half* __restrict__ addend,
    OutT* __restrict__ C)
{
    extern __shared__ __half hsm[];
    gemm_core<OutT>(X, W, bias, addend, C, hsm, blockIdx.y * HBM, blockIdx.x * HBN);
}

struct QKVArgs {
    const __half* x[3];
    const __half* w[3];
    const float*  bias[3];
    const __half* add[3];
    __half*       c[3];
};

__global__ __launch_bounds__(256, 2) void gemm_qkv(QKVArgs args)
{
    extern __shared__ __half hsm[];
    const int z = blockIdx.z;
    gemm_core<__half>(args.x[z], args.w[z], args.bias[z], args.add[z], args.c[z],
                      hsm, blockIdx.y * HBM, blockIdx.x * HBN);
}

// ========== two-pass register-softmax attention, direct normalized f32 attn ==========
#define AKP 72
#define ATK_BUFH (64 * AKP)
#define EXPC 0.180336880111f
#define AT_SMEM_BYTES ((4 * ATK_BUFH + 128) * 2)   // 37120 B

__global__ __launch_bounds__(128, 4) void attn_kernel(
    const __half* __restrict__ gq, const __half* __restrict__ gk, const __half* __restrict__ gv,
    const int* __restrict__ mask, float* __restrict__ attn, __half* __restrict__ go)
{
    extern __shared__ __half asm_[];
    __half2* msh = (__half2*)(asm_ + 4 * ATK_BUFH);   // [2][32]
    const uint32_t smb = smem_u32(asm_);

    const int tid  = threadIdx.x;
    const int wid  = tid >> 5;
    const int lane = tid & 31;
    const int gid  = lane >> 2;
    const int tig  = lane & 3;
    const int b = blockIdx.z, h = blockIdx.y;
    const int q0 = blockIdx.x * 128;

    const __half* Kb = gk + ((size_t)(b * LL)) * DD + h * DKH;
    const __half* Vb = gv + ((size_t)(b * LL)) * DD + h * DKH;

    uint32_t aq[2][4][4];
    #pragma unroll
    for (int mg = 0; mg < 2; mg++) {
        const __half* Qw = gq + ((size_t)(b * LL + q0 + wid * 32 + mg * 16)) * DD + h * DKH;
        #pragma unroll
        for (int kc = 0; kc < 4; kc++) {
            aq[mg][kc][0] = *(const uint32_t*)(Qw + (size_t)gid * DD       + kc * 16 + tig * 2);
            aq[mg][kc][1] = *(const uint32_t*)(Qw + (size_t)(gid + 8) * DD + kc * 16 + tig * 2);
            aq[mg][kc][2] = *(const uint32_t*)(Qw + (size_t)gid * DD       + kc * 16 + 8 + tig * 2);
            aq[mg][kc][3] = *(const uint32_t*)(Qw + (size_t)(gid + 8) * DD + kc * 16 + 8 + tig * 2);
        }
    }

    const int mbase = b * LL;
    const int si = lane & 7;
    const int selk = (lane >> 3) & 1;
    const int seln = (lane >> 4) & 1;

    auto stageK = [&](int kt) {
        const int buf = kt & 1;
        const __half* Ksrc = Kb + (size_t)(kt * 64) * DD;
        const uint32_t kb = smb + (uint32_t)(buf * ATK_BUFH) * 2;
        #pragma unroll
        for (int j = 0; j < 4; j++) {
            int idx = tid + 128 * j;
            int rr = idx >> 3, c8 = (idx & 7) * 8;
            cpa16h(kb + (uint32_t)(rr * AKP + c8) * 2, Ksrc + (size_t)rr * DD + c8);
        }
        asm volatile("cp.async.commit_group;\n");
    };
    auto stageKV = [&](int kt) {
        const int buf = kt & 1;
        const __half* Ksrc = Kb + (size_t)(kt * 64) * DD;
        const __half* Vsrc = Vb + (size_t)(kt * 64) * DD;
        const uint32_t kb = smb + (uint32_t)(buf * ATK_BUFH) * 2;
        const uint32_t vb = smb + (uint32_t)((2 + buf) * ATK_BUFH) * 2;
        #pragma unroll
        for (int j = 0; j < 4; j++) {
            int idx = tid + 128 * j;
            int rr = idx >> 3, c8 = (idx & 7) * 8;
            cpa16h(kb + (uint32_t)(rr * AKP + c8) * 2, Ksrc + (size_t)rr * DD + c8);
            cpa16h(vb + (uint32_t)(rr * AKP + c8) * 2, Vsrc + (size_t)rr * DD + c8);
        }
        asm volatile("cp.async.commit_group;\n");
    };

    // ================= pass 1: rowsums only =================
    float rs[2][2] = {{0.0f, 0.0f}, {0.0f, 0.0f}};
    stageK(0);
    for (int kt = 0; kt < 32; kt++) {
        const int buf = kt & 1;
        asm volatile("cp.async.wait_group 0;\n");
        if (tid < 32) {
            int m0v = mask[mbase + kt * 64 + tid * 2];
            int m1v = mask[mbase + kt * 64 + tid * 2 + 1];
            msh[buf * 32 + tid] = __halves2half2(__int2half_rn(m0v), __int2half_rn(m1v));
        }
        __syncthreads();
        if (kt + 1 < 32) stageK(kt + 1);

        const uint32_t kaddr = smb + (uint32_t)(buf * ATK_BUFH) * 2;
        const __half2* mrow = msh + buf * 32;

        #pragma unroll
        for (int ncp = 0; ncp < 4; ncp++) {
            float sc[2][2][4];
            #pragma unroll
            for (int mg = 0; mg < 2; mg++)
                #pragma unroll
                for (int n8 = 0; n8 < 2; n8++)
                    #pragma unroll
                    for (int j = 0; j < 4; j++) sc[mg][n8][j] = 0.0f;
            #pragma unroll
            for (int kc = 0; kc < 4; kc++) {
                uint32_t ad = kaddr +
                    (uint32_t)((ncp * 16 + seln * 8 + si) * AKP + kc * 16 + selk * 8) * 2;
                uint32_t b0, b1, b2, b3;
                ldmx4(b0, b1, b2, b3, ad);
                #pragma unroll
                for (int mg = 0; mg < 2; mg++) {
                    mma16816(sc[mg][0], aq[mg][kc], b0, b1);
                    mma16816(sc[mg][1], aq[mg][kc], b2, b3);
                }
            }
            #pragma unroll
            for (int mg = 0; mg < 2; mg++)
                #pragma unroll
                for (int n8 = 0; n8 < 2; n8++) {
                    __half2 m = mrow[ncp * 8 + n8 * 4 + tig];
                    uint32_t x01 = h2u(__floats2half2_rn(sc[mg][n8][0] * EXPC, sc[mg][n8][1] * EXPC));
                    uint32_t x23 = h2u(__floats2half2_rn(sc[mg][n8][2] * EXPC, sc[mg][n8][3] * EXPC));
                    uint32_t e01, e23;
                    asm("ex2.approx.f16x2 %0, %1;" : "=r"(e01) : "r"(x01));
                    asm("ex2.approx.f16x2 %0, %1;" : "=r"(e23) : "r"(x23));
                    __half2 p01 = __hmul2(u2h(e01), m);
                    __half2 p23 = __hmul2(u2h(e23), m);
                    float2 f01 = __half22float2(p01);
                    float2 f23 = __half22float2(p23);
                    rs[mg][0] += f01.x + f01.y;
                    rs[mg][1] += f23.x + f23.y;
                }
        }
    }

    float rvv[2][2];
    #pragma unroll
    for (int mg = 0; mg < 2; mg++)
        #pragma unroll
        for (int hl = 0; hl < 2; hl++) {
            rs[mg][hl] += __shfl_xor_sync(0xffffffff, rs[mg][hl], 1);
            rs[mg][hl] += __shfl_xor_sync(0xffffffff, rs[mg][hl], 2);
            rvv[mg][hl] = 1.0f / rs[mg][hl];
        }
    __syncthreads();

    // ================= pass 2: write normalized attn + O = P V =================
    float of_[2][8][4];
    #pragma unroll
    for (int mg = 0; mg < 2; mg++)
        #pragma unroll
        for (int nc = 0; nc < 8; nc++)
            #pragma unroll
            for (int j = 0; j < 4; j++) of_[mg][nc][j] = 0.0f;

    size_t arow[2][2];
    #pragma unroll
    for (int mg = 0; mg < 2; mg++) {
        arow[mg][0] = ((size_t)(b * HH + h) * LL + q0 + wid * 32 + mg * 16 + gid) * LL;
        arow[mg][1] = arow[mg][0] + 8 * (size_t)LL;
    }

    stageKV(0);
    for (int kt = 0; kt < 32; kt++) {
        const int buf = kt & 1;
        asm volatile("cp.async.wait_group 0;\n");
        if (tid < 32) {
            int m0v = mask[mbase + kt * 64 + tid * 2];
            int m1v = mask[mbase + kt * 64 + tid * 2 + 1];
            msh[buf * 32 + tid] = __halves2half2(__int2half_rn(m0v), __int2half_rn(m1v));
        }
        __syncthreads();
        if (kt + 1 < 32) stageKV(kt + 1);

        const uint32_t kaddr = smb + (uint32_t)(buf * ATK_BUFH) * 2;
        const uint32_t vaddr = smb + (uint32_t)((2 + buf) * ATK_BUFH) * 2;
        const __half2* mrow = msh + buf * 32;

        #pragma unroll
        for (int ncp = 0; ncp < 4; ncp++) {
            float sc[2][2][4];
            #pragma unroll
            for (int mg = 0; mg < 2; mg++)
                #pragma unroll
                for (int n8 = 0; n8 < 2; n8++)
                    #pragma unroll
                    for (int j = 0; j < 4; j++) sc[mg][n8][j] = 0.0f;

            #pragma unroll
            for (int kc = 0; kc < 4; kc++) {
                uint32_t ad = kaddr +
                    (uint32_t)((ncp * 16 + seln * 8 + si) * AKP + kc * 16 + selk * 8) * 2;
                uint32_t b0, b1, b2, b3;
                ldmx4(b0, b1, b2, b3, ad);
                #pragma unroll
                for (int mg = 0; mg < 2; mg++) {
                    mma16816(sc[mg][0], aq[mg][kc], b0, b1);
                    mma16816(sc[mg][1], aq[mg][kc], b2, b3);
                }
            }

            uint32_t ap[2][4];
            #pragma unroll
            for (int mg = 0; mg < 2; mg++) {
                #pragma unroll
                for (int n8 = 0; n8 < 2; n8++) {
                    __half2 m = mrow[ncp * 8 + n8 * 4 + tig];
                    uint32_t x01 = h2u(__floats2half2_rn(sc[mg][n8][0] * EXPC, sc[mg][n8][1] * EXPC));
                    uint32_t x23 = h2u(__floats2half2_rn(sc[mg][n8][2] * EXPC, sc[mg][n8][3] * EXPC));
                    uint32_t e01, e23;
                    asm("ex2.approx.f16x2 %0, %1;" : "=r"(e01) : "r"(x01));
                    asm("ex2.approx.f16x2 %0, %1;" : "=r"(e23) : "r"(x23));
                    __half2 p01 = __hmul2(u2h(e01), m);
                    __half2 p23 = __hmul2(u2h(e23), m);
                    ap[mg][n8 * 2]     = h2u(p01);
                    ap[mg][n8 * 2 + 1] = h2u(p23);
                    float2 f01 = __half22float2(p01);
                    float2 f23 = __half22float2(p23);
                    int col0 = kt * 64 + ncp * 16 + n8 * 8 + tig * 2;
                    stg_cs_f2(attn + arow[mg][0] + col0, f01.x * rvv[mg][0], f01.y * rvv[mg][0]);
                    stg_cs_f2(attn + arow[mg][1] + col0, f23.x * rvv[mg][1], f23.y * rvv[mg][1]);
                }
            }

            #pragma unroll
            for (int on = 0; on < 4; on++) {
                uint32_t ad = vaddr +
                    (uint32_t)((ncp * 16 + selk * 8 + si) * AKP + on * 16 + seln * 8) * 2;
                uint32_t b0, b1, b2, b3;
                ldmx4t(b0, b1, b2, b3, ad);
                #pragma unroll
                for (int mg = 0; mg < 2; mg++) {
                    mma16816(of_[mg][2 * on],     ap[mg], b0, b1);
                    mma16816(of_[mg][2 * on + 1], ap[mg], b2, b3);
                }
            }
        }
    }

    // O epilogue: normalize, write half
    #pragma unroll
    for (int mg = 0; mg < 2; mg++) {
        const float rv0 = rvv[mg][0];
        const float rv1 = rvv[mg][1];
        __half* go0 = go + (size_t)(b * LL + q0 + wid * 32 + mg * 16 + gid) * DD + h * DKH;
        __half* go1 = go0 + 8 * (size_t)DD;
        #pragma unroll
        for (int nc = 0; nc < 8; nc++) {
            int col0 = nc * 8 + tig * 2;
            *(uint32_t*)(go0 + col0) = h2u(__floats2half2_rn(of_[mg][nc][0] * rv0, of_[mg][nc][1] * rv0));
            *(uint32_t*)(go1 + col0) = h2u(__floats2half2_rn(of_[mg][nc][2] * rv1, of_[mg][nc][3] * rv1));
        }
    }
}

// ================= launch =================
extern "C" void kernel_launch(void* const* d_in, const int* in_sizes, int n_in,
                              void* d_out, int out_size)
{
    const float* q      = (const float*)d_in[0];
    const float* k      = (const float*)d_in[1];
    const float* v      = (const float*)d_in[2];
    const float* semf   = (const float*)d_in[3];
    const int*   mask   = (const int*)  d_in[4];
    const float* w_q    = (const float*)d_in[5];
    const float* b_q    = (const float*)d_in[6];
    const float* w_k    = (const float*)d_in[7];
    const float* b_k    = (const float*)d_in[8];
    const float* w_v    = (const float*)d_in[9];
    const float* b_v    = (const float*)d_in[10];
    const float* w_sem  = (const float*)d_in[11];
    const float* b_sem  = (const float*)d_in[12];
    const float* w_out  = (const float*)d_in[13];
    const float* b_out  = (const float*)d_in[14];

    float* out = (float*)d_out;
    const size_t attn_elems = (size_t)BB * HH * LL * LL;
    size_t attn_off = ((size_t)out_size >= attn_elems) ? (size_t)out_size - attn_elems : 0;
    float* attn = out + attn_off;

    __half *p_qx, *p_kx, *p_vx, *p_sx, *p_wq, *p_wk, *p_wv, *p_ws, *p_wo;
    __half *p_semo, *p_qp, *p_kp, *p_vp, *p_op;
    cudaGetSymbolAddress((void**)&p_qx, g_qx);
    cudaGetSymbolAddress((void**)&p_kx, g_kx);
    cudaGetSymbolAddress((void**)&p_vx, g_vx);
    cudaGetSymbolAddress((void**)&p_sx, g_sx);
    cudaGetSymbolAddress((void**)&p_wq, g_wq);
    cudaGetSymbolAddress((void**)&p_wk, g_wk);
    cudaGetSymbolAddress((void**)&p_wv, g_wv);
    cudaGetSymbolAddress((void**)&p_ws, g_ws);
    cudaGetSymbolAddress((void**)&p_wo, g_wo);
    cudaGetSymbolAddress((void**)&p_semo, g_semo);
    cudaGetSymbolAddress((void**)&p_qp, g_qp);
    cudaGetSymbolAddress((void**)&p_kp, g_kp);
    cudaGetSymbolAddress((void**)&p_vp, g_vp);
    cudaGetSymbolAddress((void**)&p_op, g_op);

    CvtArgs ca;
    ca.src[0] = (const float4*)q;    ca.dst[0] = (uint4*)p_qx;
    ca.src[1] = (const float4*)k;    ca.dst[1] = (uint4*)p_kx;
    ca.src[2] = (const float4*)v;    ca.dst[2] = (uint4*)p_vx;
    ca.src[3] = (const float4*)semf; ca.dst[3] = (uint4*)p_sx;
    ca.src[4] = (const float4*)w_q;  ca.dst[4] = (uint4*)p_wq;
    ca.src[5] = (const float4*)w_k;  ca.dst[5] = (uint4*)p_wk;
    ca.src[6] = (const float4*)w_v;  ca.dst[6] = (uint4*)p_wv;
    ca.src[7] = (const float4*)w_sem;ca.dst[7] = (uint4*)p_ws;
    ca.src[8] = (const float4*)w_out;ca.dst[8] = (uint4*)p_wo;
    cvt_all<<<16384 + 5 * 512, 256>>>(ca);

    cudaFuncSetAttribute(gemm_h<__half>, cudaFuncAttributeMaxDynamicSharedMemorySize, HSMEM_BYTES);
    cudaFuncSetAttribute(gemm_h<float>,  cudaFuncAttributeMaxDynamicSharedMemorySize, HSMEM_BYTES);
    cudaFuncSetAttribute(gemm_qkv,       cudaFuncAttributeMaxDynamicSharedMemorySize, HSMEM_BYTES);
    cudaFuncSetAttribute(attn_kernel,    cudaFuncAttributeMaxDynamicSharedMemorySize, AT_SMEM_BYTES);

    dim3 gg(GN / HBN, (BB * LL) / HBM);   // (8, 64)

    gemm_h<__half><<<gg, 256, HSMEM_BYTES>>>(p_sx, p_ws, b_sem, nullptr, p_semo);

    QKVArgs qa;
    qa.x[0] = p_qx;  qa.x[1] = p_kx;  qa.x[2] = p_vx;
    qa.w[0] = p_wq;  qa.w[1] = p_wk;  qa.w[2] = p_wv;
    qa.bias[0] = b_q; qa.bias[1] = b_k; qa.bias[2] = b_v;
    qa.add[0] = nullptr; qa.add[1] = p_semo; qa.add[2] = p_semo;
    qa.c[0] = p_qp;  qa.c[1] = p_kp;  qa.c[2] = p_vp;
    gemm_qkv<<<dim3(GN / HBN, (BB * LL) / HBM, 3), 256, HSMEM_BYTES>>>(qa);

    attn_kernel<<<dim3(LL / 128, HH, BB), 128, AT_SMEM_BYTES>>>(
        p_qp, p_kp, p_vp, mask, attn, p_op);

    gemm_h<float><<<gg, 256, HSMEM_BYTES>>>(p_op, p_wo, b_out, nullptr, out);
}

// round 17
// speedup vs baseline: 1.1087x; 1.1087x over previous
#include <cuda_runtime.h>
#include <cuda_fp16.h>
#include <cstdint>

#define BB 4
#define LL 2048
#define DD 1024
#define HH 16
#define DKH 64
#define GK 1024
#define GN 1024

// ---------------- bitcast helpers ----------------
__device__ __forceinline__ uint32_t h2u(__half2 h) {
    uint32_t u;
    *reinterpret_cast<__half2*>(&u) = h;
    return u;
}
__device__ __forceinline__ __half2 u2h(uint32_t u) {
    return *reinterpret_cast<__half2*>(&u);
}

// ---------------- scratch (static device allocations) ----------------
__device__ __half g_qx  [(size_t)BB * LL * DD];
__device__ __half g_kx  [(size_t)BB * LL * DD];
__device__ __half g_vx  [(size_t)BB * LL * DD];
__device__ __half g_sx  [(size_t)BB * LL * DD];
__device__ __half g_wq  [(size_t)DD * DD];
__device__ __half g_wk  [(size_t)DD * DD];
__device__ __half g_wv  [(size_t)DD * DD];
__device__ __half g_ws  [(size_t)DD * DD];
__device__ __half g_wo  [(size_t)DD * DD];
__device__ __half g_semo[(size_t)BB * LL * DD];
__device__ __half g_qp  [(size_t)BB * LL * DD];
__device__ __half g_kp  [(size_t)BB * LL * DD];
__device__ __half g_vp  [(size_t)BB * LL * DD];
__device__ __half g_op  [(size_t)BB * LL * DD];

// ---------------- PTX helpers ----------------
__device__ __forceinline__ void cpa16h(uint32_t saddr, const __half* src) {
    asm volatile("cp.async.cg.shared.global [%0], [%1], 16;\n" :: "r"(saddr), "l"(src));
}
__device__ __forceinline__ uint32_t smem_u32(const void* p) {
    uint32_t a;
    asm("{ .reg .u64 t; cvta.to.shared.u64 t, %1; cvt.u32.u64 %0, t; }" : "=r"(a) : "l"(p));
    return a;
}
__device__ __forceinline__ void mma16816(float* d, const uint32_t* a, uint32_t b0, uint32_t b1) {
    asm volatile(
        "mma.sync.aligned.m16n8k16.row.col.f32.f16.f16.f32 "
        "{%0,%1,%2,%3}, {%4,%5,%6,%7}, {%8,%9}, {%0,%1,%2,%3};"
        : "+f"(d[0]), "+f"(d[1]), "+f"(d[2]), "+f"(d[3])
        : "r"(a[0]), "r"(a[1]), "r"(a[2]), "r"(a[3]), "r"(b0), "r"(b1));
}
__device__ __forceinline__ void ldmx4(uint32_t& r0, uint32_t& r1, uint32_t& r2, uint32_t& r3,
                                      uint32_t addr) {
    asm volatile("ldmatrix.sync.aligned.m8n8.x4.shared.b16 {%0,%1,%2,%3}, [%4];"
                 : "=r"(r0), "=r"(r1), "=r"(r2), "=r"(r3) : "r"(addr));
}
__device__ __forceinline__ void ldmx4t(uint32_t& r0, uint32_t& r1, uint32_t& r2, uint32_t& r3,
                                       uint32_t addr) {
    asm volatile("ldmatrix.sync.aligned.m8n8.x4.trans.shared.b16 {%0,%1,%2,%3}, [%4];"
                 : "=r"(r0), "=r"(r1), "=r"(r2), "=r"(r3) : "r"(addr));
}
__device__ __forceinline__ void stg_cs_f2(void* p, float x, float y) {
    asm volatile("st.global.cs.v2.f32 [%0], {%1,%2};" :: "l"(p), "f"(x), "f"(y) : "memory");
}

// ================= fused f32 -> f16 conversion (single launch) =================
struct CvtArgs {
    const float4* src[9];
    uint4*        dst[9];
};
__global__ __launch_bounds__(256) void cvt_all(CvtArgs a)
{
    int bid = blockIdx.x;
    const float4* s;
    uint4* d;
    size_t i;
    if (bid < 16384) {
        int t = bid >> 12;
        s = a.src[t]; d = a.dst[t];
        i = (size_t)(bid & 4095) * 256 + threadIdx.x;
    } else {
        int t = 4 + ((bid - 16384) >> 9);
        s = a.src[t]; d = a.dst[t];
        i = (size_t)((bid - 16384) & 511) * 256 + threadIdx.x;
    }
    float4 x = s[i * 2], y = s[i * 2 + 1];
    uint4 o;
    o.x = h2u(__floats2half2_rn(x.x, x.y));
    o.y = h2u(__floats2half2_rn(x.z, x.w));
    o.z = h2u(__floats2half2_rn(y.x, y.y));
    o.w = h2u(__floats2half2_rn(y.z, y.w));
    d[i] = o;
}

// ===== fp16 GEMM, 128x128 tile, BK=32, 4 stages — raw ldmatrix + mma (R14) =====
#define HBM 128
#define HBN 128
#define HBK 32
#define HPAD 40
#define HNST 4
#define HNT (GK / HBK)
#define HSTG ((HBM + HBN) * HPAD)
#define HCPAD 132
#define HSMEM_BYTES (HNST * HSTG * 2)   // 81920

template <typename OutT>
__device__ __forceinline__ void gemm_core(
    const __half* __restrict__ X, const __half* __restrict__ W,
    const float* __restrict__ bias, const __half* __restrict__ addend,
    OutT* __restrict__ C, __half* hsm, int m0, int n0)
{
    const int tid  = threadIdx.x;
    const int wid  = tid >> 5;
    const int lane = tid & 31;
    const int warp_m = wid & 3;
    const int warp_n = wid >> 2;
    const int si   = lane & 7;
    const int gid  = lane >> 2;
    const int tig  = lane & 3;
    const uint32_t smb = smem_u32(hsm);

    float cacc[2][4][8];
    #pragma unroll
    for (int mt = 0; mt < 2; mt++)
        #pragma unroll
        for (int nt = 0; nt < 4; nt++)
            #pragma unroll
            for (int j = 0; j < 8; j++) cacc[mt][nt][j] = 0.0f;

    auto stage = [&](int s, int k0) {
        uint32_t base = smb + (uint32_t)(s * HSTG) * 2;
        #pragma unroll
        for (int j = 0; j < 4; j++) {
            int idx = tid + 256 * j;
            if (idx < 512) {
                int r = idx >> 2, c8 = (idx & 3) * 8;
                cpa16h(base + (uint32_t)(r * HPAD + c8) * 2,
                       X + (size_t)(m0 + r) * GK + k0 + c8);
            } else {
                int i2 = idx - 512;
                int r = i2 >> 2, c8 = (i2 & 3) * 8;
                cpa16h(base + (uint32_t)((HBM + r) * HPAD + c8) * 2,
                       W + (size_t)(n0 + r) * GK + k0 + c8);
            }
        }
        asm volatile("cp.async.commit_group;\n");
    };

    #pragma unroll
    for (int s = 0; s < HNST - 1; s++) stage(s, s * HBK);

    const int a_roff = ((lane >> 3) & 1) * 8;
    const int a_coff = ((lane >> 4) & 1) * 8;
    const int b_roff = ((lane >> 4) & 1) * 8;
    const int b_coff = ((lane >> 3) & 1) * 8;

    for (int kt = 0; kt < HNT; kt++) {
        asm volatile("cp.async.wait_group %0;\n" :: "n"(HNST - 2));
        __syncthreads();

        const int ld = kt + HNST - 1;
        if (ld < HNT) stage(ld % HNST, ld * HBK);
        else asm volatile("cp.async.commit_group;\n");

        const uint32_t sbase = smb + (uint32_t)((kt % HNST) * HSTG) * 2;

        #pragma unroll
        for (int kk = 0; kk < HBK; kk += 16) {
            uint32_t a[2][4], bf[4][4];
            #pragma unroll
            for (int mt = 0; mt < 2; mt++) {
                int row = warp_m * 32 + mt * 16 + a_roff + si;
                int col = kk + a_coff;
                ldmx4(a[mt][0], a[mt][1], a[mt][2], a[mt][3],
                      sbase + (uint32_t)(row * HPAD + col) * 2);
            }
            #pragma unroll
            for (int nt = 0; nt < 4; nt++) {
                int row = HBM + warp_n * 64 + nt * 16 + b_roff + si;
                int col = kk + b_coff;
                ldmx4(bf[nt][0], bf[nt][1], bf[nt][2], bf[nt][3],
                      sbase + (uint32_t)(row * HPAD + col) * 2);
            }
            #pragma unroll
            for (int mt = 0; mt < 2; mt++)
                #pragma unroll
                for (int nt = 0; nt < 4; nt++) {
                    mma16816(&cacc[mt][nt][0], a[mt], bf[nt][0], bf[nt][1]);
                    mma16816(&cacc[mt][nt][4], a[mt], bf[nt][2], bf[nt][3]);
                }
        }
    }

    asm volatile("cp.async.wait_group 0;\n");
    __syncthreads();

    float* Cs = (float*)hsm;
    #pragma unroll
    for (int mt = 0; mt < 2; mt++)
        #pragma unroll
        for (int nt = 0; nt < 4; nt++) {
            int rw = warp_m * 32 + mt * 16 + gid;
            int cb = warp_n * 64 + nt * 16 + tig * 2;
            Cs[rw * HCPAD + cb]           = cacc[mt][nt][0];
            Cs[rw * HCPAD + cb + 1]       = cacc[mt][nt][1];
            Cs[(rw + 8) * HCPAD + cb]     = cacc[mt][nt][2];
            Cs[(rw + 8) * HCPAD + cb + 1] = cacc[mt][nt][3];
            Cs[rw * HCPAD + cb + 8]       = cacc[mt][nt][4];
            Cs[rw * HCPAD + cb + 9]       = cacc[mt][nt][5];
            Cs[(rw + 8) * HCPAD + cb + 8] = cacc[mt][nt][6];
            Cs[(rw + 8) * HCPAD + cb + 9] = cacc[mt][nt][7];
        }
    __syncthreads();

    const int c4 = (tid & 31) * 4;
    const int r0 = tid >> 5;
    float4 bv = *(const float4*)(bias + n0 + c4);
    #pragma unroll
    for (int it = 0; it < 16; it++) {
        int rr = r0 + it * 8;
        size_t gi = (size_t)(m0 + rr) * GN + n0 + c4;
        float4 val = *(const float4*)(Cs + rr * HCPAD + c4);
        val.x += bv.x; val.y += bv.y; val.z += bv.z; val.w += bv.w;
        if (addend) {
            uint2 au = *(const uint2*)(addend + gi);
            __half2 a01 = u2h(au.x), a23 = u2h(au.y);
            val.x += __low2float(a01);  val.y += __high2float(a01);
            val.z += __low2float(a23);  val.w += __high2float(a23);
        }
        if (sizeof(OutT) == 2) {
            uint2 o;
            o.x = h2u(__floats2half2_rn(val.x, val.y));
            o.y = h2u(__floats2half2_rn(val.z, val.w));
            *(uint2*)((__half*)C + gi) = o;
        } else {
            *(float4*)((float*)C + gi) = val;
        }
    }
}

template <typename OutT>
__global__ __launch_bounds__(256, 2) void gemm_h(
    const __half* __restrict__ X, const __half* __restrict__ W,
    const float* __restrict__ bias, const __half* __restrict__ addend,
    OutT* __restrict__ C)
{
    extern __shared__ __half hsm[];
    gemm_core<OutT>(X, W, bias, addend, C, hsm, blockIdx.y * HBM, blockIdx.x * HBN);
}

struct QKVArgs {
    const __half* x[3];
    const __half* w[3];
    const float*  bias[3];
    const __half* add[3];
    __half*       c[3];
};

__global__ __launch_bounds__(256, 2) void gemm_qkv(QKVArgs args)
{
    extern __shared__ __half hsm[];
    const int z = blockIdx.z;
    gemm_core<__half>(args.x[z], args.w[z], args.bias[z], args.add[z], args.c[z],
                      hsm, blockIdx.y * HBM, blockIdx.x * HBN);
}

// ========== two-pass register-softmax attention, direct normalized f32 attn ==========
// pass 1: 4-deep K-only pipeline; pass 2: K+V double-buffered (R15)
#define AKP 72
#define ATK_BUFH (64 * AKP)
#define EXPC 0.180336880111f
#define AT_SMEM_BYTES ((4 * ATK_BUFH + 256) * 2)

__global__ __launch_bounds__(128, 3) void attn_kernel(
    const __half* __restrict__ gq, const __half* __restrict__ gk, const __half* __restrict__ gv,
    const int* __restrict__ mask, float* __restrict__ attn, __half* __restrict__ go)
{
    extern __shared__ __half asm_[];
    __half2* msh = (__half2*)(asm_ + 4 * ATK_BUFH);   // [4][32]
    const uint32_t smb = smem_u32(asm_);

    const int tid  = threadIdx.x;
    const int wid  = tid >> 5;
    const int lane = tid & 31;
    const int gid  = lane >> 2;
    const int tig  = lane & 3;
    const int b = blockIdx.z, h = blockIdx.y;
    const int q0 = blockIdx.x * 128;

    const __half* Kb = gk + ((size_t)(b * LL)) * DD + h * DKH;
    const __half* Vb = gv + ((size_t)(b * LL)) * DD + h * DKH;

    uint32_t aq[2][4][4];
    #pragma unroll
    for (int mg = 0; mg < 2; mg++) {
        const __half* Qw = gq + ((size_t)(b * LL + q0 + wid * 32 + mg * 16)) * DD + h * DKH;
        #pragma unroll
        for (int kc = 0; kc < 4; kc++) {
            aq[mg][kc][0] = *(const uint32_t*)(Qw + (size_t)gid * DD       + kc * 16 + tig * 2);
            aq[mg][kc][1] = *(const uint32_t*)(Qw + (size_t)(gid + 8) * DD + kc * 16 + tig * 2);
            aq[mg][kc][2] = *(const uint32_t*)(Qw + (size_t)gid * DD       + kc * 16 + 8 + tig * 2);
            aq[mg][kc][3] = *(const uint32_t*)(Qw + (size_t)(gid + 8) * DD + kc * 16 + 8 + tig * 2);
        }
    }

    const int mbase = b * LL;
    const int si = lane & 7;
    const int selk = (lane >> 3) & 1;
    const int seln = (lane >> 4) & 1;

    // pass-1: K into buffer kt&3 (all 4 tile buffers)
    auto stageK4 = [&](int kt) {
        const int buf = kt & 3;
        const __half* Ksrc = Kb + (size_t)(kt * 64) * DD;
        const uint32_t kb = smb + (uint32_t)(buf * ATK_BUFH) * 2;
        #pragma unroll
        for (int j = 0; j < 4; j++) {
            int idx = tid + 128 * j;
            int rr = idx >> 3, c8 = (idx & 7) * 8;
            cpa16h(kb + (uint32_t)(rr * AKP + c8) * 2, Ksrc + (size_t)rr * DD + c8);
        }
        asm volatile("cp.async.commit_group;\n");
    };
    // pass-2: K+V double-buffered
    auto stageKV = [&](int kt) {
        const int buf = kt & 1;
        const __half* Ksrc = Kb + (size_t)(kt * 64) * DD;
        const __half* Vsrc = Vb + (size_t)(kt * 64) * DD;
        const uint32_t kb = smb + (uint32_t)(buf * ATK_BUFH) * 2;
        const uint32_t vb = smb + (uint32_t)((2 + buf) * ATK_BUFH) * 2;
        #pragma unroll
        for (int j = 0; j < 4; j++) {
            int idx = tid + 128 * j;
            int rr = idx >> 3, c8 = (idx & 7) * 8;
            cpa16h(kb + (uint32_t)(rr * AKP + c8) * 2, Ksrc + (size_t)rr * DD + c8);
            cpa16h(vb + (uint32_t)(rr * AKP + c8) * 2, Vsrc + (size_t)rr * DD + c8);
        }
        asm volatile("cp.async.commit_group;\n");
    };

    // ================= pass 1: rowsums only (4-deep pipeline) =================
    float rs[2][2] = {{0.0f, 0.0f}, {0.0f, 0.0f}};
    stageK4(0); stageK4(1); stageK4(2);
    for (int kt = 0; kt < 32; kt++) {
        const int buf = kt & 3;
        asm volatile("cp.async.wait_group 2;\n");
        if (tid < 32) {
            int m0v = mask[mbase + kt * 64 + tid * 2];
            int m1v = mask[mbase + kt * 64 + tid * 2 + 1];
            msh[buf * 32 + tid] = __halves2half2(__int2half_rn(m0v), __int2half_rn(m1v));
        }
        __syncthreads();
        if (kt + 3 < 32) stageK4(kt + 3);
        else asm volatile("cp.async.commit_group;\n");

        const uint32_t kaddr = smb + (uint32_t)(buf * ATK_BUFH) * 2;
        const __half2* mrow = msh + buf * 32;

        #pragma unroll
        for (int ncp = 0; ncp < 4; ncp++) {
            float sc[2][2][4];
            #pragma unroll
            for (int mg = 0; mg < 2; mg++)
                #pragma unroll
                for (int n8 = 0; n8 < 2; n8++)
                    #pragma unroll
                    for (int j = 0; j < 4; j++) sc[mg][n8][j] = 0.0f;
            #pragma unroll
            for (int kc = 0; kc < 4; kc++) {
                uint32_t ad = kaddr +
                    (uint32_t)((ncp * 16 + seln * 8 + si) * AKP + kc * 16 + selk * 8) * 2;
                uint32_t b0, b1, b2, b3;
                ldmx4(b0, b1, b2, b3, ad);
                #pragma unroll
                for (int mg = 0; mg < 2; mg++) {
                    mma16816(sc[mg][0], aq[mg][kc], b0, b1);
                    mma16816(sc[mg][1], aq[mg][kc], b2, b3);
                }
            }
            #pragma unroll
            for (int mg = 0; mg < 2; mg++)
                #pragma unroll
                for (int n8 = 0; n8 < 2; n8++) {
                    __half2 m = mrow[ncp * 8 + n8 * 4 + tig];
                    uint32_t x01 = h2u(__floats2half2_rn(sc[mg][n8][0] * EXPC, sc[mg][n8][1] * EXPC));
                    uint32_t x23 = h2u(__floats2half2_rn(sc[mg][n8][2] * EXPC, sc[mg][n8][3] * EXPC));
                    uint32_t e01, e23;
                    asm("ex2.approx.f16x2 %0, %1;" : "=r"(e01) : "r"(x01));
                    asm("ex2.approx.f16x2 %0, %1;" : "=r"(e23) : "r"(x23));
                    __half2 p01 = __hmul2(u2h(e01), m);
                    __half2 p23 = __hmul2(u2h(e23), m);
                    float2 f01 = __half22float2(p01);
                    float2 f23 = __half22float2(p23);
                    rs[mg][0] += f01.x + f01.y;
                    rs[mg][1] += f23.x + f23.y;
                }
        }
    }

    float rvv[2][2];
    #pragma unroll
    for (int mg = 0; mg < 2; mg++)
        #pragma unroll
        for (int hl = 0; hl < 2; hl++) {
            rs[mg][hl] += __shfl_xor_sync(0xffffffff, rs[mg][hl], 1);
            rs[mg][hl] += __shfl_xor_sync(0xffffffff, rs[mg][hl], 2);
            rvv[mg][hl] = 1.0f / rs[mg][hl];
        }
    asm volatile("cp.async.wait_group 0;\n");
    __syncthreads();

    // ================= pass 2: write normalized attn + O = P V =================
    float of_[2][8][4];
    #pragma unroll
    for (int mg = 0; mg < 2; mg++)
        #pragma unroll
        for (int nc = 0; nc < 8; nc++)
            #pragma unroll
            for (int j = 0; j < 4; j++) of_[mg][nc][j] = 0.0f;

    size_t arow[2][2];
    #pragma unroll
    for (int mg = 0; mg < 2; mg++) {
        arow[mg][0] = ((size_t)(b * HH + h) * LL + q0 + wid * 32 + mg * 16 + gid) * LL;
        arow[mg][1] = arow[mg][0] + 8 * (size_t)LL;
    }

    stageKV(0);
    for (int kt = 0; kt < 32; kt++) {
        const int buf = kt & 1;
        asm volatile("cp.async.wait_group 0;\n");
        if (tid < 32) {
            int m0v = mask[mbase + kt * 64 + tid * 2];
            int m1v = mask[mbase + kt * 64 + tid * 2 + 1];
            msh[buf * 32 + tid] = __halves2half2(__int2half_rn(m0v), __int2half_rn(m1v));
        }
        __syncthreads();
        if (kt + 1 < 32) stageKV(kt + 1);

        const uint32_t kaddr = smb + (uint32_t)(buf * ATK_BUFH) * 2;
        const uint32_t vaddr = smb + (uint32_t)((2 + buf) * ATK_BUFH) * 2;
        const __half2* mrow = msh + buf * 32;

        #pragma unroll
        for (int ncp = 0; ncp < 4; ncp++) {
            float sc[2][2][4];
            #pragma unroll
            for (int mg = 0; mg < 2; mg++)
                #pragma unroll
                for (int n8 = 0; n8 < 2; n8++)
                    #pragma unroll
                    for (int j = 0; j < 4; j++) sc[mg][n8][j] = 0.0f;

            #pragma unroll
            for (int kc = 0; kc < 4; kc++) {
                uint32_t ad = kaddr +
                    (uint32_t)((ncp * 16 + seln * 8 + si) * AKP + kc * 16 + selk * 8) * 2;
                uint32_t b0, b1, b2, b3;
                ldmx4(b0, b1, b2, b3, ad);
                #pragma unroll
                for (int mg = 0; mg < 2; mg++) {
                    mma16816(sc[mg][0], aq[mg][kc], b0, b1);
                    mma16816(sc[mg][1], aq[mg][kc], b2, b3);
                }
            }

            uint32_t ap[2][4];
            #pragma unroll
            for (int mg = 0; mg < 2; mg++) {
                #pragma unroll
                for (int n8 = 0; n8 < 2; n8++) {
                    __half2 m = mrow[ncp * 8 + n8 * 4 + tig];
                    uint32_t x01 = h2u(__floats2half2_rn(sc[mg][n8][0] * EXPC, sc[mg][n8][1] * EXPC));
                    uint32_t x23 = h2u(__floats2half2_rn(sc[mg][n8][2] * EXPC, sc[mg][n8][3] * EXPC));
                    uint32_t e01, e23;
                    asm("ex2.approx.f16x2 %0, %1;" : "=r"(e01) : "r"(x01));
                    asm("ex2.approx.f16x2 %0, %1;" : "=r"(e23) : "r"(x23));
                    __half2 p01 = __hmul2(u2h(e01), m);
                    __half2 p23 = __hmul2(u2h(e23), m);
                    ap[mg][n8 * 2]     = h2u(p01);
                    ap[mg][n8 * 2 + 1] = h2u(p23);
                    float2 f01 = __half22float2(p01);
                    float2 f23 = __half22float2(p23);
                    int col0 = kt * 64 + ncp * 16 + n8 * 8 + tig * 2;
                    stg_cs_f2(attn + arow[mg][0] + col0, f01.x * rvv[mg][0], f01.y * rvv[mg][0]);
                    stg_cs_f2(attn + arow[mg][1] + col0, f23.x * rvv[mg][1], f23.y * rvv[mg][1]);
                }
            }

            #pragma unroll
            for (int on = 0; on < 4; on++) {
                uint32_t ad = vaddr +
                    (uint32_t)((ncp * 16 + selk * 8 + si) * AKP + on * 16 + seln * 8) * 2;
                uint32_t b0, b1, b2, b3;
                ldmx4t(b0, b1, b2, b3, ad);
                #pragma unroll
                for (int mg = 0; mg < 2; mg++) {
                    mma16816(of_[mg][2 * on],     ap[mg], b0, b1);
                    mma16816(of_[mg][2 * on + 1], ap[mg], b2, b3);
                }
            }
        }
    }

    // O epilogue: normalize, write half
    #pragma unroll
    for (int mg = 0; mg < 2; mg++) {
        const float rv0 = rvv[mg][0];
        const float rv1 = rvv[mg][1];
        __half* go0 = go + (size_t)(b * LL + q0 + wid * 32 + mg * 16 + gid) * DD + h * DKH;
        __half* go1 = go0 + 8 * (size_t)DD;
        #pragma unroll
        for (int nc = 0; nc < 8; nc++) {
            int col0 = nc * 8 + tig * 2;
            *(uint32_t*)(go0 + col0) = h2u(__floats2half2_rn(of_[mg][nc][0] * rv0, of_[mg][nc][1] * rv0));
            *(uint32_t*)(go1 + col0) = h2u(__floats2half2_rn(of_[mg][nc][2] * rv1, of_[mg][nc][3] * rv1));
        }
    }
}

// ================= launch =================
extern "C" void kernel_launch(void* const* d_in, const int* in_sizes, int n_in,
                              void* d_out, int out_size)
{
    const float* q      = (const float*)d_in[0];
    const float* k      = (const float*)d_in[1];
    const float* v      = (const float*)d_in[2];
    const float* semf   = (const float*)d_in[3];
    const int*   mask   = (const int*)  d_in[4];
    const float* w_q    = (const float*)d_in[5];
    const float* b_q    = (const float*)d_in[6];
    const float* w_k    = (const float*)d_in[7];
    const float* b_k    = (const float*)d_in[8];
    const float* w_v    = (const float*)d_in[9];
    const float* b_v    = (const float*)d_in[10];
    const float* w_sem  = (const float*)d_in[11];
    const float* b_sem  = (const float*)d_in[12];
    const float* w_out  = (const float*)d_in[13];
    const float* b_out  = (const float*)d_in[14];

    float* out = (float*)d_out;
    const size_t attn_elems = (size_t)BB * HH * LL * LL;
    size_t attn_off = ((size_t)out_size >= attn_elems) ? (size_t)out_size - attn_elems : 0;
    float* attn = out + attn_off;

    __half *p_qx, *p_kx, *p_vx, *p_sx, *p_wq, *p_wk, *p_wv, *p_ws, *p_wo;
    __half *p_semo, *p_qp, *p_kp, *p_vp, *p_op;
    cudaGetSymbolAddress((void**)&p_qx, g_qx);
    cudaGetSymbolAddress((void**)&p_kx, g_kx);
    cudaGetSymbolAddress((void**)&p_vx, g_vx);
    cudaGetSymbolAddress((void**)&p_sx, g_sx);
    cudaGetSymbolAddress((void**)&p_wq, g_wq);
    cudaGetSymbolAddress((void**)&p_wk, g_wk);
    cudaGetSymbolAddress((void**)&p_wv, g_wv);
    cudaGetSymbolAddress((void**)&p_ws, g_ws);
    cudaGetSymbolAddress((void**)&p_wo, g_wo);
    cudaGetSymbolAddress((void**)&p_semo, g_semo);
    cudaGetSymbolAddress((void**)&p_qp, g_qp);
    cudaGetSymbolAddress((void**)&p_kp, g_kp);
    cudaGetSymbolAddress((void**)&p_vp, g_vp);
    cudaGetSymbolAddress((void**)&p_op, g_op);

    CvtArgs ca;
    ca.src[0] = (const float4*)q;    ca.dst[0] = (uint4*)p_qx;
    ca.src[1] = (const float4*)k;    ca.dst[1] = (uint4*)p_kx;
    ca.src[2] = (const float4*)v;    ca.dst[2] = (uint4*)p_vx;
    ca.src[3] = (const float4*)semf; ca.dst[3] = (uint4*)p_sx;
    ca.src[4] = (const float4*)w_q;  ca.dst[4] = (uint4*)p_wq;
    ca.src[5] = (const float4*)w_k;  ca.dst[5] = (uint4*)p_wk;
    ca.src[6] = (const float4*)w_v;  ca.dst[6] = (uint4*)p_wv;
    ca.src[7] = (const float4*)w_sem;ca.dst[7] = (uint4*)p_ws;
    ca.src[8] = (const float4*)w_out;ca.dst[8] = (uint4*)p_wo;
    cvt_all<<<16384 + 5 * 512, 256>>>(ca);

    cudaFuncSetAttribute(gemm_h<__half>, cudaFuncAttributeMaxDynamicSharedMemorySize, HSMEM_BYTES);
    cudaFuncSetAttribute(gemm_h<float>,  cudaFuncAttributeMaxDynamicSharedMemorySize, HSMEM_BYTES);
    cudaFuncSetAttribute(gemm_qkv,       cudaFuncAttributeMaxDynamicSharedMemorySize, HSMEM_BYTES);
    cudaFuncSetAttribute(attn_kernel,    cudaFuncAttributeMaxDynamicSharedMemorySize, AT_SMEM_BYTES);

    dim3 gg(GN / HBN, (BB * LL) / HBM);   // (8, 64)

    gemm_h<__half><<<gg, 256, HSMEM_BYTES>>>(p_sx, p_ws, b_sem, nullptr, p_semo);

    QKVArgs qa;
    qa.x[0] = p_qx;  qa.x[1] = p_kx;  qa.x[2] = p_vx;
    qa.w[0] = p_wq;  qa.w[1] = p_wk;  qa.w[2] = p_wv;
    qa.bias[0] = b_q; qa.bias[1] = b_k; qa.bias[2] = b_v;
    qa.add[0] = nullptr; qa.add[1] = p_semo; qa.add[2] = p_semo;
    qa.c[0] = p_qp;  qa.c[1] = p_kp;  qa.c[2] = p_vp;
    gemm_qkv<<<dim3(GN / HBN, (BB * LL) / HBM, 3), 256, HSMEM_BYTES>>>(qa);

    attn_kernel<<<dim3(LL / 128, HH, BB), 128, AT_SMEM_BYTES>>>(
        p_qp, p_kp, p_vp, mask, attn, p_op);

    gemm_h<float><<<gg, 256, HSMEM_BYTES>>>(p_op, p_wo, b_out, nullptr, out);
}